// round 3
// baseline (speedup 1.0000x reference)
#include <cuda_runtime.h>
#include <stdint.h>
#include <math.h>
#include <stddef.h>

#define BB 4
#define V0 4096
#define V1 1024
#define V2 256
#define NEI 20

// ---------------- scratch (__device__ globals; no allocation allowed) ----------------
__device__ float g_sd0[3*128];
__device__ float g_sd1[3*256];
__device__ float g_sd2[3*512];
__device__ float g_sd3[3*1024];
__device__ float g_sd4[3*4096];
__device__ int   g_sel1[V1];
__device__ int   g_sel2[V2];
__device__ int   g_idx0[BB*V0*NEI];
__device__ float g_nd0[BB*V0*NEI*3];
__device__ float g_fm0[BB*V0*32];
__device__ float g_f1[BB*V0*320];
__device__ float g_fm1[BB*V0*64];
__device__ float g_v1[BB*V1*3];
__device__ float g_fm1p[BB*V1*64];
__device__ int   g_idx1[BB*V1*NEI];
__device__ float g_nd1[BB*V1*NEI*3];
__device__ float g_f2[BB*V1*640];
__device__ float g_fm2[BB*V1*128];
__device__ float g_f3[BB*V1*1280];
__device__ float g_fm3[BB*V1*256];
__device__ float g_v2[BB*V2*3];
__device__ float g_fm3p[BB*V2*256];
__device__ int   g_idx2[BB*V2*NEI];
__device__ float g_nd2[BB*V2*NEI*3];
__device__ float g_f4[BB*V2*5120];
__device__ float g_fm4[BB*V2*1024];

// ---------------- threefry2x32 (JAX-compatible, 20 rounds) ----------------
__device__ __forceinline__ uint32_t rotl32(uint32_t v, int r) {
    return (v << r) | (v >> (32 - r));
}

__device__ __forceinline__ void tf2x32(uint32_t k0, uint32_t k1,
                                       uint32_t x0, uint32_t x1,
                                       uint32_t& o0, uint32_t& o1) {
    uint32_t k2 = k0 ^ k1 ^ 0x1BD11BDAu;
    x0 += k0; x1 += k1;
#define TFR(r) { x0 += x1; x1 = rotl32(x1, r); x1 ^= x0; }
    TFR(13) TFR(15) TFR(26) TFR(6)   x0 += k1; x1 += k2 + 1u;
    TFR(17) TFR(29) TFR(16) TFR(24)  x0 += k2; x1 += k0 + 2u;
    TFR(13) TFR(15) TFR(26) TFR(6)   x0 += k0; x1 += k1 + 3u;
    TFR(17) TFR(29) TFR(16) TFR(24)  x0 += k1; x1 += k2 + 4u;
    TFR(13) TFR(15) TFR(26) TFR(6)   x0 += k2; x1 += k0 + 5u;
#undef TFR
    o0 = x0; o1 = x1;
}

// jax.random.permutation(key(seed), n)[:nsel]
// _shuffle: per round: key,subkey = split(key); bits = random_bits(subkey,32,(n,));
//           stable sort_key_val(bits, x).
// Partitionable threefry (JAX default since 0.4.36):
//   split (foldlike): newkey = block(key,0,0); subkey = block(key,0,1)
//   random_bits 32-bit: bits[i] = o0 ^ o1 of block(subkey, hi=0, lo=i)   <-- R2 FIX
// Stable sort reproduced via 64-bit composite (bits<<24 | pos<<12 | val), bitonic.
__global__ void perm_kernel(int n, uint32_t seed, int* sel, int nsel, int nrounds) {
    __shared__ unsigned long long arr[4096];
    int tid = threadIdx.x, NT = blockDim.x;
    int vals[4];
    for (int t = 0; t < 4; t++) { int i = tid + t*NT; if (i < n) vals[t] = i; }
    uint32_t k0 = 0u, k1 = seed;
    for (int r = 0; r < nrounds; r++) {
        uint32_t nk0, nk1, sk0, sk1;
        tf2x32(k0, k1, 0u, 0u, nk0, nk1);   // new key = block(key,0,0)
        tf2x32(k0, k1, 0u, 1u, sk0, sk1);   // subkey  = block(key,0,1)
        k0 = nk0; k1 = nk1;
        for (int t = 0; t < 4; t++) {
            int i = tid + t*NT;
            if (i < n) {
                uint32_t o0, o1;
                tf2x32(sk0, sk1, 0u, (uint32_t)i, o0, o1);
                uint32_t bits = o0 ^ o1;  // partitionable 32-bit fold: bits1 ^ bits2
                arr[i] = ((unsigned long long)bits << 24) |
                         ((unsigned long long)(unsigned)i << 12) |
                         (unsigned long long)(unsigned)vals[t];
            }
        }
        __syncthreads();
        for (int k = 2; k <= n; k <<= 1) {
            for (int j = k >> 1; j > 0; j >>= 1) {
                for (int t = 0; t < 4; t++) {
                    int i = tid + t*NT;
                    if (i < n) {
                        int ixj = i ^ j;
                        if (ixj > i && ixj < n) {
                            unsigned long long a = arr[i], c = arr[ixj];
                            bool up = ((i & k) == 0);
                            if ((a > c) == up) { arr[i] = c; arr[ixj] = a; }
                        }
                    }
                }
                __syncthreads();
            }
        }
        for (int t = 0; t < 4; t++) {
            int i = tid + t*NT;
            if (i < n) vals[t] = (int)(arr[i] & 0xFFFull);
        }
        __syncthreads();
    }
    for (int t = 0; t < 4; t++) { int i = tid + t*NT; if (i < nsel) sel[i] = vals[t]; }
}

// ---------------- normalize columns of a (3, E) matrix ----------------
__global__ void normcols_kernel(const float* __restrict__ src, float* __restrict__ dst, int E) {
    int e = blockIdx.x * blockDim.x + threadIdx.x;
    if (e >= E) return;
    float a = src[e], b = src[E + e], c = src[2*E + e];
    float nn = sqrtf(a*a + b*b + c*c);
    nn = fmaxf(nn, 1e-12f);
    dst[e] = a / nn; dst[E + e] = b / nn; dst[2*E + e] = c / nn;
}

// ---------------- KNN: one block per (vertex, batch), 20 argmin rounds ----------------
__global__ void knn_kernel(const float* __restrict__ verts, int* __restrict__ idx_out, int VN) {
    extern __shared__ float sdist[];
    __shared__ float wv[8];
    __shared__ int   wi[8];
    int i = blockIdx.x, b = blockIdx.y;
    const float* vb = verts + (size_t)b * VN * 3;
    float vix = vb[i*3+0], viy = vb[i*3+1], viz = vb[i*3+2];
    float sqi = vix*vix + viy*viy + viz*viz;
    const float FINF = __int_as_float(0x7f800000);
    for (int j = threadIdx.x; j < VN; j += blockDim.x) {
        float x = vb[j*3+0], y = vb[j*3+1], z = vb[j*3+2];
        float d = sqi + (x*x + y*y + z*z) - 2.f*(vix*x + viy*y + viz*z);
        sdist[j] = (j == i) ? FINF : d;
    }
    __syncthreads();
    int lane = threadIdx.x & 31, warp = threadIdx.x >> 5;
    int nw = blockDim.x >> 5;
    for (int r = 0; r < NEI; r++) {
        float best = FINF; int bi = 0x7fffffff;
        for (int j = threadIdx.x; j < VN; j += blockDim.x) {
            float d = sdist[j];
            if (d < best) { best = d; bi = j; }
        }
        for (int off = 16; off; off >>= 1) {
            float ov = __shfl_down_sync(0xffffffffu, best, off);
            int   oi = __shfl_down_sync(0xffffffffu, bi, off);
            if (ov < best || (ov == best && oi < bi)) { best = ov; bi = oi; }
        }
        if (lane == 0) { wv[warp] = best; wi[warp] = bi; }
        __syncthreads();
        if (threadIdx.x == 0) {
            float bb2 = wv[0]; int bbi = wi[0];
            for (int w = 1; w < nw; w++)
                if (wv[w] < bb2 || (wv[w] == bb2 && wi[w] < bbi)) { bb2 = wv[w]; bbi = wi[w]; }
            idx_out[((size_t)b * VN + i) * NEI + r] = bbi;
            sdist[bbi] = FINF;
        }
        __syncthreads();
    }
}

// ---------------- normalized neighbor directions ----------------
__global__ void nd_kernel(const float* __restrict__ verts, const int* __restrict__ idx,
                          float* __restrict__ nd, int VN) {
    int t = blockIdx.x * blockDim.x + threadIdx.x;
    int total = BB * VN * NEI;
    if (t >= total) return;
    int v = (t / NEI) % VN;
    int b = t / (NEI * VN);
    int j = idx[t];
    const float* vb = verts + (size_t)b * VN * 3;
    float dx = vb[j*3+0] - vb[v*3+0];
    float dy = vb[j*3+1] - vb[v*3+1];
    float dz = vb[j*3+2] - vb[v*3+2];
    float nn = sqrtf(dx*dx + dy*dy + dz*dz);
    nn = fmaxf(nn, 1e-12f);
    nd[3*t+0] = dx / nn; nd[3*t+1] = dy / nn; nd[3*t+2] = dz / nn;
}

// ---------------- conv_surface: fm0[b,v,c] = relu( sum_s max_n relu(nd . sd[:,s*32+c]) ) ----------------
__global__ void conv_surface_kernel(const float* __restrict__ nd, const float* __restrict__ sd,
                                    float* __restrict__ fm0) {
    int v = blockIdx.x, b = blockIdx.y;
    __shared__ float snd[NEI*3];
    __shared__ float sm[128];
    int tid = threadIdx.x;  // e in [0,128)
    size_t base = ((size_t)b * V0 + v) * NEI;
    if (tid < NEI*3) snd[tid] = nd[base*3 + tid];
    __syncthreads();
    float s0 = sd[tid], s1 = sd[128 + tid], s2 = sd[256 + tid];
    float m = -__int_as_float(0x7f800000);
    #pragma unroll
    for (int n = 0; n < NEI; n++) {
        float th = snd[3*n]*s0 + snd[3*n+1]*s1 + snd[3*n+2]*s2;
        th = fmaxf(th, 0.f);
        m = fmaxf(m, th);
    }
    sm[tid] = m;
    __syncthreads();
    if (tid < 32) {
        float r = sm[tid] + sm[32 + tid] + sm[64 + tid] + sm[96 + tid];
        fm0[((size_t)b * V0 + v) * 32 + tid] = fmaxf(r, 0.f);
    }
}

// ---------------- GEMM + bias: C[m,e] = sum_k A[m,k] W[k,e] + bias[e] ----------------
// 64x64 tile, 256 threads, 4x4 microtile. M,N multiples of 64; K multiple of 16.
__global__ void gemm_bias_kernel(const float* __restrict__ A, const float* __restrict__ W,
                                 const float* __restrict__ bias, float* __restrict__ C,
                                 int M, int K, int N) {
    __shared__ float As[16][65];
    __shared__ float Bs[16][64];
    int bn = blockIdx.x * 64, bm = blockIdx.y * 64;
    int tid = threadIdx.x;
    int tx = tid & 15, ty = tid >> 4;
    float acc[4][4];
    #pragma unroll
    for (int j = 0; j < 4; j++) {
        float bv = bias[bn + tx + 16*j];
        #pragma unroll
        for (int i = 0; i < 4; i++) acc[i][j] = bv;
    }
    for (int k0 = 0; k0 < K; k0 += 16) {
        #pragma unroll
        for (int q = 0; q < 4; q++) {
            int p = tid + 256*q;
            int mm = p >> 4, kk = p & 15;
            As[kk][mm] = A[(size_t)(bm + mm) * K + k0 + kk];
        }
        #pragma unroll
        for (int q = 0; q < 4; q++) {
            int p = tid + 256*q;
            int kk = p >> 6, nn = p & 63;
            Bs[kk][nn] = W[(size_t)(k0 + kk) * N + bn + nn];
        }
        __syncthreads();
        #pragma unroll
        for (int kk = 0; kk < 16; kk++) {
            float a[4], bv[4];
            #pragma unroll
            for (int i = 0; i < 4; i++) a[i] = As[kk][ty + 16*i];
            #pragma unroll
            for (int j = 0; j < 4; j++) bv[j] = Bs[kk][tx + 16*j];
            #pragma unroll
            for (int i = 0; i < 4; i++)
                #pragma unroll
                for (int j = 0; j < 4; j++) acc[i][j] += a[i] * bv[j];
        }
        __syncthreads();
    }
    #pragma unroll
    for (int i = 0; i < 4; i++)
        #pragma unroll
        for (int j = 0; j < 4; j++)
            C[(size_t)(bm + ty + 16*i) * N + bn + tx + 16*j] = acc[i][j];
}

// ---------------- conv_layer aggregation ----------------
// out[b,v,c] = f[b,v,c] + sum_s max_n relu(nd . sd[:, s*C+c]) * f[b,idx[n], C + s*C + c]
__global__ void conv_layer_kernel(const float* __restrict__ f, const int* __restrict__ idx,
                                  const float* __restrict__ nd, const float* __restrict__ sd,
                                  float* __restrict__ out, int VN, int C, int do_relu) {
    int v = blockIdx.x, b = blockIdx.y;
    __shared__ float snd[NEI*3];
    __shared__ int   sidx[NEI];
    int tid = threadIdx.x;
    size_t base = ((size_t)b * VN + v) * NEI;
    if (tid < NEI)   sidx[tid] = idx[base + tid];
    if (tid < NEI*3) snd[tid]  = nd[base*3 + tid];
    __syncthreads();
    const float* fb = f + (size_t)b * VN * 5 * C;
    int C4 = 4 * C;
    const float NINF = -__int_as_float(0x7f800000);
    for (int c = tid; c < C; c += blockDim.x) {
        float sx0 = sd[0*C4 + 0*C + c], sx1 = sd[0*C4 + 1*C + c],
              sx2 = sd[0*C4 + 2*C + c], sx3 = sd[0*C4 + 3*C + c];
        float sy0 = sd[1*C4 + 0*C + c], sy1 = sd[1*C4 + 1*C + c],
              sy2 = sd[1*C4 + 2*C + c], sy3 = sd[1*C4 + 3*C + c];
        float sz0 = sd[2*C4 + 0*C + c], sz1 = sd[2*C4 + 1*C + c],
              sz2 = sd[2*C4 + 2*C + c], sz3 = sd[2*C4 + 3*C + c];
        float a0 = NINF, a1 = NINF, a2 = NINF, a3 = NINF;
        #pragma unroll 4
        for (int n = 0; n < NEI; n++) {
            float dx = snd[3*n], dy = snd[3*n+1], dz = snd[3*n+2];
            const float* fj = fb + (size_t)sidx[n] * 5 * C + C + c;
            float t0 = fmaxf(dx*sx0 + dy*sy0 + dz*sz0, 0.f);
            float t1 = fmaxf(dx*sx1 + dy*sy1 + dz*sz1, 0.f);
            float t2 = fmaxf(dx*sx2 + dy*sy2 + dz*sz2, 0.f);
            float t3 = fmaxf(dx*sx3 + dy*sy3 + dz*sz3, 0.f);
            a0 = fmaxf(a0, t0 * fj[0]);
            a1 = fmaxf(a1, t1 * fj[C]);
            a2 = fmaxf(a2, t2 * fj[2*C]);
            a3 = fmaxf(a3, t3 * fj[3*C]);
        }
        float r = fb[(size_t)v * 5 * C + c] + ((a0 + a1) + (a2 + a3));
        out[((size_t)b * VN + v) * C + c] = do_relu ? fmaxf(r, 0.f) : r;
    }
}

// ---------------- pool: max over neighbors of selected rows ----------------
__global__ void pool_kernel(const float* __restrict__ verts, const float* __restrict__ fm,
                            const int* __restrict__ idx, const int* __restrict__ sel,
                            float* __restrict__ vout, float* __restrict__ fout,
                            int VN, int C, int VOUT) {
    int i = blockIdx.x, b = blockIdx.y;
    __shared__ int sidx[NEI];
    __shared__ int sr;
    if (threadIdx.x == 0) sr = sel[i];
    __syncthreads();
    int r = sr;
    if (threadIdx.x < NEI) sidx[threadIdx.x] = idx[((size_t)b * VN + r) * NEI + threadIdx.x];
    if (threadIdx.x < 3)
        vout[((size_t)b * VOUT + i) * 3 + threadIdx.x] = verts[((size_t)b * VN + r) * 3 + threadIdx.x];
    __syncthreads();
    const float NINF = -__int_as_float(0x7f800000);
    for (int c = threadIdx.x; c < C; c += blockDim.x) {
        float m = NINF;
        #pragma unroll 4
        for (int n = 0; n < NEI; n++)
            m = fmaxf(m, fm[((size_t)b * VN + sidx[n]) * C + c]);
        fout[((size_t)b * VOUT + i) * C + c] = m;
    }
}

// ---------------- final transpose: (b, v, c) -> (b, c, v) ----------------
__global__ void transpose_kernel(const float* __restrict__ fm4, float* __restrict__ out) {
    __shared__ float tile[32][33];
    int b = blockIdx.z;
    int v0 = blockIdx.x * 32, c0 = blockIdx.y * 32;
    int x = threadIdx.x, y = threadIdx.y;
    for (int yy = y; yy < 32; yy += 8)
        tile[yy][x] = fm4[((size_t)b * V2 + v0 + yy) * 1024 + c0 + x];
    __syncthreads();
    for (int yy = y; yy < 32; yy += 8)
        out[((size_t)b * 1024 + c0 + yy) * V2 + v0 + x] = tile[x][yy];
}

// ---------------- launch ----------------
extern "C" void kernel_launch(void* const* d_in, const int* in_sizes, int n_in,
                              void* d_out, int out_size) {
    const float* verts = (const float*)d_in[0];
    const float* dirs0 = (const float*)d_in[1];
    const float* W1 = (const float*)d_in[2];
    const float* b1 = (const float*)d_in[3];
    const float* D1 = (const float*)d_in[4];
    const float* W2 = (const float*)d_in[5];
    const float* b2 = (const float*)d_in[6];
    const float* D2 = (const float*)d_in[7];
    const float* W3 = (const float*)d_in[8];
    const float* b3 = (const float*)d_in[9];
    const float* D3 = (const float*)d_in[10];
    const float* W4 = (const float*)d_in[11];
    const float* b4 = (const float*)d_in[12];
    const float* D4 = (const float*)d_in[13];
    float* out = (float*)d_out;

    float *sd0, *sd1, *sd2, *sd3, *sd4;
    float *nd0, *nd1, *nd2;
    float *fm0, *f1, *fm1, *v1, *fm1p, *f2, *fm2, *f3, *fm3, *v2, *fm3p, *f4, *fm4;
    int *sel1, *sel2, *idx0, *idx1, *idx2;
    cudaGetSymbolAddress((void**)&sd0, g_sd0);
    cudaGetSymbolAddress((void**)&sd1, g_sd1);
    cudaGetSymbolAddress((void**)&sd2, g_sd2);
    cudaGetSymbolAddress((void**)&sd3, g_sd3);
    cudaGetSymbolAddress((void**)&sd4, g_sd4);
    cudaGetSymbolAddress((void**)&sel1, g_sel1);
    cudaGetSymbolAddress((void**)&sel2, g_sel2);
    cudaGetSymbolAddress((void**)&idx0, g_idx0);
    cudaGetSymbolAddress((void**)&idx1, g_idx1);
    cudaGetSymbolAddress((void**)&idx2, g_idx2);
    cudaGetSymbolAddress((void**)&nd0, g_nd0);
    cudaGetSymbolAddress((void**)&nd1, g_nd1);
    cudaGetSymbolAddress((void**)&nd2, g_nd2);
    cudaGetSymbolAddress((void**)&fm0, g_fm0);
    cudaGetSymbolAddress((void**)&f1, g_f1);
    cudaGetSymbolAddress((void**)&fm1, g_fm1);
    cudaGetSymbolAddress((void**)&v1, g_v1);
    cudaGetSymbolAddress((void**)&fm1p, g_fm1p);
    cudaGetSymbolAddress((void**)&f2, g_f2);
    cudaGetSymbolAddress((void**)&fm2, g_fm2);
    cudaGetSymbolAddress((void**)&f3, g_f3);
    cudaGetSymbolAddress((void**)&fm3, g_fm3);
    cudaGetSymbolAddress((void**)&v2, g_v2);
    cudaGetSymbolAddress((void**)&fm3p, g_fm3p);
    cudaGetSymbolAddress((void**)&f4, g_f4);
    cudaGetSymbolAddress((void**)&fm4, g_fm4);

    // normalized direction bases
    normcols_kernel<<<1, 128>>>(dirs0, sd0, 128);
    normcols_kernel<<<2, 128>>>(D1, sd1, 256);
    normcols_kernel<<<4, 128>>>(D2, sd2, 512);
    normcols_kernel<<<8, 128>>>(D3, sd3, 1024);
    normcols_kernel<<<32, 128>>>(D4, sd4, 4096);

    // pooling permutations (data-independent; must match jax.random exactly)
    perm_kernel<<<1, 1024>>>(4096, 42u, sel1, V1, 2);
    perm_kernel<<<1, 1024>>>(1024, 43u, sel2, V2, 1);

    // stage A (4096 verts)
    knn_kernel<<<dim3(V0, BB), 256, V0 * sizeof(float)>>>(verts, idx0, V0);
    {
        int tot = BB * V0 * NEI;
        nd_kernel<<<(tot + 255) / 256, 256>>>(verts, idx0, nd0, V0);
    }
    conv_surface_kernel<<<dim3(V0, BB), 128>>>(nd0, sd0, fm0);
    gemm_bias_kernel<<<dim3(320 / 64, BB * V0 / 64), 256>>>(fm0, W1, b1, f1, BB * V0, 32, 320);
    conv_layer_kernel<<<dim3(V0, BB), 64>>>(f1, idx0, nd0, sd1, fm1, V0, 64, 1);
    pool_kernel<<<dim3(V1, BB), 64>>>(verts, fm1, idx0, sel1, v1, fm1p, V0, 64, V1);

    // stage B (1024 verts)
    knn_kernel<<<dim3(V1, BB), 256, V1 * sizeof(float)>>>(v1, idx1, V1);
    {
        int tot = BB * V1 * NEI;
        nd_kernel<<<(tot + 255) / 256, 256>>>(v1, idx1, nd1, V1);
    }
    gemm_bias_kernel<<<dim3(640 / 64, BB * V1 / 64), 256>>>(fm1p, W2, b2, f2, BB * V1, 64, 640);
    conv_layer_kernel<<<dim3(V1, BB), 128>>>(f2, idx1, nd1, sd2, fm2, V1, 128, 1);
    gemm_bias_kernel<<<dim3(1280 / 64, BB * V1 / 64), 256>>>(fm2, W3, b3, f3, BB * V1, 128, 1280);
    conv_layer_kernel<<<dim3(V1, BB), 256>>>(f3, idx1, nd1, sd3, fm3, V1, 256, 1);
    pool_kernel<<<dim3(V2, BB), 256>>>(v1, fm3, idx1, sel2, v2, fm3p, V1, 256, V2);

    // stage C (256 verts)
    knn_kernel<<<dim3(V2, BB), 256, V2 * sizeof(float)>>>(v2, idx2, V2);
    {
        int tot = BB * V2 * NEI;
        nd_kernel<<<(tot + 255) / 256, 256>>>(v2, idx2, nd2, V2);
    }
    gemm_bias_kernel<<<dim3(5120 / 64, BB * V2 / 64), 256>>>(fm3p, W4, b4, f4, BB * V2, 256, 5120);
    conv_layer_kernel<<<dim3(V2, BB), 256>>>(f4, idx2, nd2, sd4, fm4, V2, 1024, 0);

    // output transpose (b, v, c) -> (b, c, v, 1)
    transpose_kernel<<<dim3(V2 / 32, 1024 / 32, BB), dim3(32, 8)>>>(fm4, out);
}

// round 4
// speedup vs baseline: 1.0604x; 1.0604x over previous
#include <cuda_runtime.h>
#include <stdint.h>
#include <math.h>
#include <stddef.h>

#define BB 4
#define V0 4096
#define V1 1024
#define V2 256
#define NEI 20

// ---------------- scratch (__device__ globals; no allocation allowed) ----------------
__device__ float g_sd0[3*128];
__device__ float g_sd1[3*256];
__device__ float g_sd2[3*512];
__device__ float g_sd3[3*1024];
__device__ float g_sd4[3*4096];
__device__ int   g_sel1[V1];
__device__ int   g_sel2[V2];
__device__ int   g_idx0[BB*V0*NEI];
__device__ float g_nd0[BB*V0*NEI*3];
__device__ float g_fm0[BB*V0*32];
__device__ float g_f1[BB*V0*320];
__device__ float g_fm1[BB*V0*64];
__device__ float g_v1[BB*V1*3];
__device__ float g_fm1p[BB*V1*64];
__device__ int   g_idx1[BB*V1*NEI];
__device__ float g_nd1[BB*V1*NEI*3];
__device__ float g_f2[BB*V1*640];
__device__ float g_fm2[BB*V1*128];
__device__ float g_f3[BB*V1*1280];
__device__ float g_fm3[BB*V1*256];
__device__ float g_v2[BB*V2*3];
__device__ float g_fm3p[BB*V2*256];
__device__ int   g_idx2[BB*V2*NEI];
__device__ float g_nd2[BB*V2*NEI*3];
__device__ float g_f4[BB*V2*5120];
__device__ float g_fm4[BB*V2*1024];

// ---------------- threefry2x32 (JAX-compatible, 20 rounds) ----------------
__device__ __forceinline__ uint32_t rotl32(uint32_t v, int r) {
    return (v << r) | (v >> (32 - r));
}

__device__ __forceinline__ void tf2x32(uint32_t k0, uint32_t k1,
                                       uint32_t x0, uint32_t x1,
                                       uint32_t& o0, uint32_t& o1) {
    uint32_t k2 = k0 ^ k1 ^ 0x1BD11BDAu;
    x0 += k0; x1 += k1;
#define TFR(r) { x0 += x1; x1 = rotl32(x1, r); x1 ^= x0; }
    TFR(13) TFR(15) TFR(26) TFR(6)   x0 += k1; x1 += k2 + 1u;
    TFR(17) TFR(29) TFR(16) TFR(24)  x0 += k2; x1 += k0 + 2u;
    TFR(13) TFR(15) TFR(26) TFR(6)   x0 += k0; x1 += k1 + 3u;
    TFR(17) TFR(29) TFR(16) TFR(24)  x0 += k1; x1 += k2 + 4u;
    TFR(13) TFR(15) TFR(26) TFR(6)   x0 += k2; x1 += k0 + 5u;
#undef TFR
    o0 = x0; o1 = x1;
}

// jax.random.permutation(key(seed), n)[:nsel]  (partitionable threefry; verified R3)
__global__ void perm_kernel(int n, uint32_t seed, int* sel, int nsel, int nrounds) {
    __shared__ unsigned long long arr[4096];
    int tid = threadIdx.x, NT = blockDim.x;
    int vals[4];
    for (int t = 0; t < 4; t++) { int i = tid + t*NT; if (i < n) vals[t] = i; }
    uint32_t k0 = 0u, k1 = seed;
    for (int r = 0; r < nrounds; r++) {
        uint32_t nk0, nk1, sk0, sk1;
        tf2x32(k0, k1, 0u, 0u, nk0, nk1);   // new key = block(key,0,0)
        tf2x32(k0, k1, 0u, 1u, sk0, sk1);   // subkey  = block(key,0,1)
        k0 = nk0; k1 = nk1;
        for (int t = 0; t < 4; t++) {
            int i = tid + t*NT;
            if (i < n) {
                uint32_t o0, o1;
                tf2x32(sk0, sk1, 0u, (uint32_t)i, o0, o1);
                uint32_t bits = o0 ^ o1;  // partitionable 32-bit fold
                arr[i] = ((unsigned long long)bits << 24) |
                         ((unsigned long long)(unsigned)i << 12) |
                         (unsigned long long)(unsigned)vals[t];
            }
        }
        __syncthreads();
        for (int k = 2; k <= n; k <<= 1) {
            for (int j = k >> 1; j > 0; j >>= 1) {
                for (int t = 0; t < 4; t++) {
                    int i = tid + t*NT;
                    if (i < n) {
                        int ixj = i ^ j;
                        if (ixj > i && ixj < n) {
                            unsigned long long a = arr[i], c = arr[ixj];
                            bool up = ((i & k) == 0);
                            if ((a > c) == up) { arr[i] = c; arr[ixj] = a; }
                        }
                    }
                }
                __syncthreads();
            }
        }
        for (int t = 0; t < 4; t++) {
            int i = tid + t*NT;
            if (i < n) vals[t] = (int)(arr[i] & 0xFFFull);
        }
        __syncthreads();
    }
    for (int t = 0; t < 4; t++) { int i = tid + t*NT; if (i < nsel) sel[i] = vals[t]; }
}

// ---------------- fused column-normalize of all five (3,E) direction matrices ----------------
__global__ void normcols_all_kernel(const float* __restrict__ s0, float* __restrict__ d0,
                                    const float* __restrict__ s1, float* __restrict__ d1,
                                    const float* __restrict__ s2, float* __restrict__ d2,
                                    const float* __restrict__ s3, float* __restrict__ d3,
                                    const float* __restrict__ s4, float* __restrict__ d4) {
    int seg = blockIdx.y;
    const float* src; float* dst; int E;
    switch (seg) {
        case 0: src = s0; dst = d0; E = 128; break;
        case 1: src = s1; dst = d1; E = 256; break;
        case 2: src = s2; dst = d2; E = 512; break;
        case 3: src = s3; dst = d3; E = 1024; break;
        default: src = s4; dst = d4; E = 4096; break;
    }
    int e = blockIdx.x * blockDim.x + threadIdx.x;
    if (e >= E) return;
    float a = src[e], b = src[E + e], c = src[2*E + e];
    float nn = sqrtf(a*a + b*b + c*c);
    nn = fmaxf(nn, 1e-12f);
    dst[e] = a / nn; dst[E + e] = b / nn; dst[2*E + e] = c / nn;
}

// ---------------- KNN: one block per (vertex, batch), 20 argmin rounds ----------------
__global__ void knn_kernel(const float* __restrict__ verts, int* __restrict__ idx_out, int VN) {
    extern __shared__ float sdist[];
    __shared__ float wv[8];
    __shared__ int   wi[8];
    int i = blockIdx.x, b = blockIdx.y;
    const float* vb = verts + (size_t)b * VN * 3;
    float vix = vb[i*3+0], viy = vb[i*3+1], viz = vb[i*3+2];
    float sqi = vix*vix + viy*viy + viz*viz;
    const float FINF = __int_as_float(0x7f800000);
    for (int j = threadIdx.x; j < VN; j += blockDim.x) {
        float x = vb[j*3+0], y = vb[j*3+1], z = vb[j*3+2];
        float d = sqi + (x*x + y*y + z*z) - 2.f*(vix*x + viy*y + viz*z);
        sdist[j] = (j == i) ? FINF : d;
    }
    __syncthreads();
    int lane = threadIdx.x & 31, warp = threadIdx.x >> 5;
    int nw = blockDim.x >> 5;
    for (int r = 0; r < NEI; r++) {
        float best = FINF; int bi = 0x7fffffff;
        for (int j = threadIdx.x; j < VN; j += blockDim.x) {
            float d = sdist[j];
            if (d < best) { best = d; bi = j; }
        }
        for (int off = 16; off; off >>= 1) {
            float ov = __shfl_down_sync(0xffffffffu, best, off);
            int   oi = __shfl_down_sync(0xffffffffu, bi, off);
            if (ov < best || (ov == best && oi < bi)) { best = ov; bi = oi; }
        }
        if (lane == 0) { wv[warp] = best; wi[warp] = bi; }
        __syncthreads();
        if (threadIdx.x == 0) {
            float bb2 = wv[0]; int bbi = wi[0];
            for (int w = 1; w < nw; w++)
                if (wv[w] < bb2 || (wv[w] == bb2 && wi[w] < bbi)) { bb2 = wv[w]; bbi = wi[w]; }
            idx_out[((size_t)b * VN + i) * NEI + r] = bbi;
            sdist[bbi] = FINF;
        }
        __syncthreads();
    }
}

// ---------------- normalized neighbor directions ----------------
__global__ void nd_kernel(const float* __restrict__ verts, const int* __restrict__ idx,
                          float* __restrict__ nd, int VN) {
    int t = blockIdx.x * blockDim.x + threadIdx.x;
    int total = BB * VN * NEI;
    if (t >= total) return;
    int v = (t / NEI) % VN;
    int b = t / (NEI * VN);
    int j = idx[t];
    const float* vb = verts + (size_t)b * VN * 3;
    float dx = vb[j*3+0] - vb[v*3+0];
    float dy = vb[j*3+1] - vb[v*3+1];
    float dz = vb[j*3+2] - vb[v*3+2];
    float nn = sqrtf(dx*dx + dy*dy + dz*dz);
    nn = fmaxf(nn, 1e-12f);
    nd[3*t+0] = dx / nn; nd[3*t+1] = dy / nn; nd[3*t+2] = dz / nn;
}

// ---------------- conv_surface: 8 vertices per block, sd held in registers ----------------
#define CS_VPB 8
__global__ void conv_surface_kernel(const float* __restrict__ nd, const float* __restrict__ sd,
                                    float* __restrict__ fm0) {
    int v0 = blockIdx.x * CS_VPB, b = blockIdx.y;
    __shared__ float snd[CS_VPB][NEI*3];
    __shared__ float sm[CS_VPB][128];
    int tid = threadIdx.x;  // 128 threads, tid = e
    size_t base = ((size_t)b * V0 + v0) * NEI * 3;
    for (int i = tid; i < CS_VPB*NEI*3; i += 128)
        snd[i / (NEI*3)][i % (NEI*3)] = nd[base + i];
    __syncthreads();
    float s0 = sd[tid], s1 = sd[128 + tid], s2 = sd[256 + tid];
    const float NINF = -__int_as_float(0x7f800000);
    #pragma unroll
    for (int vv = 0; vv < CS_VPB; vv++) {
        float m = NINF;
        #pragma unroll
        for (int n = 0; n < NEI; n++) {
            float th = snd[vv][3*n]*s0 + snd[vv][3*n+1]*s1 + snd[vv][3*n+2]*s2;
            m = fmaxf(m, fmaxf(th, 0.f));
        }
        sm[vv][tid] = m;
    }
    __syncthreads();
    for (int i = tid; i < CS_VPB*32; i += 128) {
        int vv = i >> 5, c = i & 31;
        float r = sm[vv][c] + sm[vv][32 + c] + sm[vv][64 + c] + sm[vv][96 + c];
        fm0[((size_t)b * V0 + v0 + vv) * 32 + c] = fmaxf(r, 0.f);
    }
}

// ---------------- GEMM + bias: C[m,e] = sum_k A[m,k] W[k,e] + bias[e] ----------------
// 128x64 tile, 256 threads, 8x4 microtile, float4 everywhere.
// Requirements: M%128==0, N%64==0, K%16==0 (all shapes here satisfy this).
__global__ void gemm_bias_kernel(const float* __restrict__ A, const float* __restrict__ W,
                                 const float* __restrict__ bias, float* __restrict__ C,
                                 int M, int K, int N) {
    __shared__ float As[16][132];  // k-major, padded (132*4B keeps 16B alignment)
    __shared__ float Bs[16][64];
    int bn = blockIdx.x * 64, bm = blockIdx.y * 128;
    int tid = threadIdx.x;
    int tx = tid & 15, ty = tid >> 4;       // tx: n-group, ty: m-group
    float acc[8][4];
    #pragma unroll
    for (int j = 0; j < 4; j++) {
        float bv = bias[bn + tx*4 + j];
        #pragma unroll
        for (int i = 0; i < 8; i++) acc[i][j] = bv;
    }
    int mmA = tid >> 2;          // 0..63
    int kk4 = (tid & 3) * 4;     // 0,4,8,12
    int kkB = tid >> 4;          // 0..15
    int nn4 = (tid & 15) * 4;    // 0..60
    for (int k0 = 0; k0 < K; k0 += 16) {
        #pragma unroll
        for (int q = 0; q < 2; q++) {
            int mm = mmA + 64*q;
            float4 av = *(const float4*)&A[(size_t)(bm + mm) * K + k0 + kk4];
            As[kk4+0][mm] = av.x; As[kk4+1][mm] = av.y;
            As[kk4+2][mm] = av.z; As[kk4+3][mm] = av.w;
        }
        *(float4*)&Bs[kkB][nn4] = *(const float4*)&W[(size_t)(k0 + kkB) * N + bn + nn4];
        __syncthreads();
        #pragma unroll
        for (int kk = 0; kk < 16; kk++) {
            float a[8], bv[4];
            *(float4*)&a[0] = *(const float4*)&As[kk][ty*8];
            *(float4*)&a[4] = *(const float4*)&As[kk][ty*8 + 4];
            *(float4*)&bv[0] = *(const float4*)&Bs[kk][tx*4];
            #pragma unroll
            for (int i = 0; i < 8; i++)
                #pragma unroll
                for (int j = 0; j < 4; j++) acc[i][j] += a[i] * bv[j];
        }
        __syncthreads();
    }
    #pragma unroll
    for (int i = 0; i < 8; i++) {
        float4 o = make_float4(acc[i][0], acc[i][1], acc[i][2], acc[i][3]);
        *(float4*)&C[(size_t)(bm + ty*8 + i) * N + bn + tx*4] = o;
    }
}

// ---------------- conv_layer aggregation (VPB vertices per 256-thread block) ----------------
// out[b,v,c] = f[b,v,c] + sum_s max_n relu(nd . sd[:, s*C+c]) * f[b,idx[n], C + s*C + c]
__global__ void conv_layer_kernel(const float* __restrict__ f, const int* __restrict__ idx,
                                  const float* __restrict__ nd, const float* __restrict__ sd,
                                  float* __restrict__ out, int VN, int C, int do_relu,
                                  int VPB, int CT) {
    int b = blockIdx.y;
    int v0 = blockIdx.x * VPB;
    __shared__ float snd[4*NEI*3];
    __shared__ int   sidx[4*NEI];
    int tid = threadIdx.x;  // 256
    size_t ibase = ((size_t)b * VN + v0) * NEI;
    for (int i = tid; i < VPB*NEI; i += 256)   sidx[i] = idx[ibase + i];
    for (int i = tid; i < VPB*NEI*3; i += 256) snd[i]  = nd[ibase*3 + i];
    __syncthreads();
    int vloc = tid / CT;
    int v = v0 + vloc;
    const float* fb = f + (size_t)b * VN * 5 * C;
    const float* myS = snd + vloc * NEI * 3;
    const int*   myI = sidx + vloc * NEI;
    int C4 = 4 * C;
    const float NINF = -__int_as_float(0x7f800000);
    for (int c = tid % CT; c < C; c += CT) {
        float sx0 = sd[0*C4 + 0*C + c], sx1 = sd[0*C4 + 1*C + c],
              sx2 = sd[0*C4 + 2*C + c], sx3 = sd[0*C4 + 3*C + c];
        float sy0 = sd[1*C4 + 0*C + c], sy1 = sd[1*C4 + 1*C + c],
              sy2 = sd[1*C4 + 2*C + c], sy3 = sd[1*C4 + 3*C + c];
        float sz0 = sd[2*C4 + 0*C + c], sz1 = sd[2*C4 + 1*C + c],
              sz2 = sd[2*C4 + 2*C + c], sz3 = sd[2*C4 + 3*C + c];
        float a0 = NINF, a1 = NINF, a2 = NINF, a3 = NINF;
        #pragma unroll 4
        for (int n = 0; n < NEI; n++) {
            float dx = myS[3*n], dy = myS[3*n+1], dz = myS[3*n+2];
            const float* fj = fb + (size_t)myI[n] * 5 * C + C + c;
            float t0 = fmaxf(dx*sx0 + dy*sy0 + dz*sz0, 0.f);
            float t1 = fmaxf(dx*sx1 + dy*sy1 + dz*sz1, 0.f);
            float t2 = fmaxf(dx*sx2 + dy*sy2 + dz*sz2, 0.f);
            float t3 = fmaxf(dx*sx3 + dy*sy3 + dz*sz3, 0.f);
            a0 = fmaxf(a0, t0 * fj[0]);
            a1 = fmaxf(a1, t1 * fj[C]);
            a2 = fmaxf(a2, t2 * fj[2*C]);
            a3 = fmaxf(a3, t3 * fj[3*C]);
        }
        float r = fb[(size_t)v * 5 * C + c] + ((a0 + a1) + (a2 + a3));
        out[((size_t)b * VN + v) * C + c] = do_relu ? fmaxf(r, 0.f) : r;
    }
}

// ---------------- pool: max over neighbors of selected rows (VPB rows per block) ----------------
__global__ void pool_kernel(const float* __restrict__ verts, const float* __restrict__ fm,
                            const int* __restrict__ idx, const int* __restrict__ sel,
                            float* __restrict__ vout, float* __restrict__ fout,
                            int VN, int C, int VOUT, int VPB, int CT) {
    int i0 = blockIdx.x * VPB, b = blockIdx.y;
    __shared__ int sidx[4][NEI];
    __shared__ int sr[4];
    int tid = threadIdx.x;  // 256
    int vloc = tid / CT, lc = tid % CT;
    if (lc == 0) sr[vloc] = sel[i0 + vloc];
    __syncthreads();
    int r = sr[vloc];
    if (lc < NEI) sidx[vloc][lc] = idx[((size_t)b * VN + r) * NEI + lc];
    if (lc < 3)
        vout[((size_t)b * VOUT + i0 + vloc) * 3 + lc] = verts[((size_t)b * VN + r) * 3 + lc];
    __syncthreads();
    const float NINF = -__int_as_float(0x7f800000);
    for (int c = lc; c < C; c += CT) {
        float m = NINF;
        #pragma unroll 4
        for (int n = 0; n < NEI; n++)
            m = fmaxf(m, fm[((size_t)b * VN + sidx[vloc][n]) * C + c]);
        fout[((size_t)b * VOUT + i0 + vloc) * C + c] = m;
    }
}

// ---------------- final transpose: (b, v, c) -> (b, c, v) ----------------
__global__ void transpose_kernel(const float* __restrict__ fm4, float* __restrict__ out) {
    __shared__ float tile[32][33];
    int b = blockIdx.z;
    int v0 = blockIdx.x * 32, c0 = blockIdx.y * 32;
    int x = threadIdx.x, y = threadIdx.y;
    for (int yy = y; yy < 32; yy += 8)
        tile[yy][x] = fm4[((size_t)b * V2 + v0 + yy) * 1024 + c0 + x];
    __syncthreads();
    for (int yy = y; yy < 32; yy += 8)
        out[((size_t)b * 1024 + c0 + yy) * V2 + v0 + x] = tile[x][yy];
}

// ---------------- launch ----------------
extern "C" void kernel_launch(void* const* d_in, const int* in_sizes, int n_in,
                              void* d_out, int out_size) {
    const float* verts = (const float*)d_in[0];
    const float* dirs0 = (const float*)d_in[1];
    const float* W1 = (const float*)d_in[2];
    const float* b1 = (const float*)d_in[3];
    const float* D1 = (const float*)d_in[4];
    const float* W2 = (const float*)d_in[5];
    const float* b2 = (const float*)d_in[6];
    const float* D2 = (const float*)d_in[7];
    const float* W3 = (const float*)d_in[8];
    const float* b3 = (const float*)d_in[9];
    const float* D3 = (const float*)d_in[10];
    const float* W4 = (const float*)d_in[11];
    const float* b4 = (const float*)d_in[12];
    const float* D4 = (const float*)d_in[13];
    float* out = (float*)d_out;

    float *sd0, *sd1, *sd2, *sd3, *sd4;
    float *nd0, *nd1, *nd2;
    float *fm0, *f1, *fm1, *v1, *fm1p, *f2, *fm2, *f3, *fm3, *v2, *fm3p, *f4, *fm4;
    int *sel1, *sel2, *idx0, *idx1, *idx2;
    cudaGetSymbolAddress((void**)&sd0, g_sd0);
    cudaGetSymbolAddress((void**)&sd1, g_sd1);
    cudaGetSymbolAddress((void**)&sd2, g_sd2);
    cudaGetSymbolAddress((void**)&sd3, g_sd3);
    cudaGetSymbolAddress((void**)&sd4, g_sd4);
    cudaGetSymbolAddress((void**)&sel1, g_sel1);
    cudaGetSymbolAddress((void**)&sel2, g_sel2);
    cudaGetSymbolAddress((void**)&idx0, g_idx0);
    cudaGetSymbolAddress((void**)&idx1, g_idx1);
    cudaGetSymbolAddress((void**)&idx2, g_idx2);
    cudaGetSymbolAddress((void**)&nd0, g_nd0);
    cudaGetSymbolAddress((void**)&nd1, g_nd1);
    cudaGetSymbolAddress((void**)&nd2, g_nd2);
    cudaGetSymbolAddress((void**)&fm0, g_fm0);
    cudaGetSymbolAddress((void**)&f1, g_f1);
    cudaGetSymbolAddress((void**)&fm1, g_fm1);
    cudaGetSymbolAddress((void**)&v1, g_v1);
    cudaGetSymbolAddress((void**)&fm1p, g_fm1p);
    cudaGetSymbolAddress((void**)&f2, g_f2);
    cudaGetSymbolAddress((void**)&fm2, g_fm2);
    cudaGetSymbolAddress((void**)&f3, g_f3);
    cudaGetSymbolAddress((void**)&fm3, g_fm3);
    cudaGetSymbolAddress((void**)&v2, g_v2);
    cudaGetSymbolAddress((void**)&fm3p, g_fm3p);
    cudaGetSymbolAddress((void**)&f4, g_f4);
    cudaGetSymbolAddress((void**)&fm4, g_fm4);

    // [0] normalized direction bases (fused)
    normcols_all_kernel<<<dim3(32, 5), 128>>>(dirs0, sd0, D1, sd1, D2, sd2, D3, sd3, D4, sd4);

    // stage A (4096 verts)
    // [1..5] — hot kernels early so the fixed ncu window (-s 5 -c 1) lands on real work
    knn_kernel<<<dim3(V0, BB), 256, V0 * sizeof(float)>>>(verts, idx0, V0);
    nd_kernel<<<(BB*V0*NEI + 255) / 256, 256>>>(verts, idx0, nd0, V0);
    conv_surface_kernel<<<dim3(V0 / CS_VPB, BB), 128>>>(nd0, sd0, fm0);
    gemm_bias_kernel<<<dim3(320/64, BB*V0/128), 256>>>(fm0, W1, b1, f1, BB*V0, 32, 320);
    conv_layer_kernel<<<dim3(V0/4, BB), 256>>>(f1, idx0, nd0, sd1, fm1, V0, 64, 1, 4, 64);

    // pooling permutations (data-independent; must match jax.random exactly)
    perm_kernel<<<1, 1024>>>(4096, 42u, sel1, V1, 2);
    pool_kernel<<<dim3(V1/4, BB), 256>>>(verts, fm1, idx0, sel1, v1, fm1p, V0, 64, V1, 4, 64);

    // stage B (1024 verts)
    knn_kernel<<<dim3(V1, BB), 256, V1 * sizeof(float)>>>(v1, idx1, V1);
    nd_kernel<<<(BB*V1*NEI + 255) / 256, 256>>>(v1, idx1, nd1, V1);
    gemm_bias_kernel<<<dim3(640/64, BB*V1/128), 256>>>(fm1p, W2, b2, f2, BB*V1, 64, 640);
    conv_layer_kernel<<<dim3(V1/2, BB), 256>>>(f2, idx1, nd1, sd2, fm2, V1, 128, 1, 2, 128);
    gemm_bias_kernel<<<dim3(1280/64, BB*V1/128), 256>>>(fm2, W3, b3, f3, BB*V1, 128, 1280);
    conv_layer_kernel<<<dim3(V1, BB), 256>>>(f3, idx1, nd1, sd3, fm3, V1, 256, 1, 1, 256);
    perm_kernel<<<1, 1024>>>(1024, 43u, sel2, V2, 1);
    pool_kernel<<<dim3(V2, BB), 256>>>(v1, fm3, idx1, sel2, v2, fm3p, V1, 256, V2, 1, 256);

    // stage C (256 verts)
    knn_kernel<<<dim3(V2, BB), 256, V2 * sizeof(float)>>>(v2, idx2, V2);
    nd_kernel<<<(BB*V2*NEI + 255) / 256, 256>>>(v2, idx2, nd2, V2);
    gemm_bias_kernel<<<dim3(5120/64, BB*V2/128), 256>>>(fm3p, W4, b4, f4, BB*V2, 256, 5120);
    conv_layer_kernel<<<dim3(V2, BB), 256>>>(f4, idx2, nd2, sd4, fm4, V2, 1024, 0, 1, 256);

    // output transpose (b, v, c) -> (b, c, v, 1)
    transpose_kernel<<<dim3(V2 / 32, 1024 / 32, BB), dim3(32, 8)>>>(fm4, out);
}

// round 5
// speedup vs baseline: 1.9317x; 1.8217x over previous
#include <cuda_runtime.h>
#include <stdint.h>
#include <math.h>
#include <stddef.h>

#define BB 4
#define V0 4096
#define V1 1024
#define V2 256
#define NEI 20

// ---------------- scratch (__device__ globals; no allocation allowed) ----------------
__device__ float g_sd0[3*128];
__device__ float g_sd1[3*256];
__device__ float g_sd2[3*512];
__device__ float g_sd3[3*1024];
__device__ float g_sd4[3*4096];
__device__ int   g_sel1[V1];
__device__ int   g_sel2[V2];
__device__ int   g_idx0[BB*V0*NEI];
__device__ float g_nd0[BB*V0*NEI*3];
__device__ float g_fm0[BB*V0*32];
__device__ float g_f1[BB*V0*320];
__device__ float g_fm1[BB*V0*64];
__device__ float g_v1[BB*V1*3];
__device__ float g_fm1p[BB*V1*64];
__device__ int   g_idx1[BB*V1*NEI];
__device__ float g_nd1[BB*V1*NEI*3];
__device__ float g_f2[BB*V1*640];
__device__ float g_fm2[BB*V1*128];
__device__ float g_f3[BB*V1*1280];
__device__ float g_fm3[BB*V1*256];
__device__ float g_v2[BB*V2*3];
__device__ float g_fm3p[BB*V2*256];
__device__ int   g_idx2[BB*V2*NEI];
__device__ float g_nd2[BB*V2*NEI*3];
__device__ float g_f4[BB*V2*5120];
__device__ float g_fm4[BB*V2*1024];

// ---------------- threefry2x32 (JAX-compatible, 20 rounds) ----------------
__device__ __forceinline__ uint32_t rotl32(uint32_t v, int r) {
    return (v << r) | (v >> (32 - r));
}

__device__ __forceinline__ void tf2x32(uint32_t k0, uint32_t k1,
                                       uint32_t x0, uint32_t x1,
                                       uint32_t& o0, uint32_t& o1) {
    uint32_t k2 = k0 ^ k1 ^ 0x1BD11BDAu;
    x0 += k0; x1 += k1;
#define TFR(r) { x0 += x1; x1 = rotl32(x1, r); x1 ^= x0; }
    TFR(13) TFR(15) TFR(26) TFR(6)   x0 += k1; x1 += k2 + 1u;
    TFR(17) TFR(29) TFR(16) TFR(24)  x0 += k2; x1 += k0 + 2u;
    TFR(13) TFR(15) TFR(26) TFR(6)   x0 += k0; x1 += k1 + 3u;
    TFR(17) TFR(29) TFR(16) TFR(24)  x0 += k1; x1 += k2 + 4u;
    TFR(13) TFR(15) TFR(26) TFR(6)   x0 += k2; x1 += k0 + 5u;
#undef TFR
    o0 = x0; o1 = x1;
}

// jax.random.permutation(key(seed), n)[:nsel]  (partitionable threefry; verified R3)
__global__ void perm_kernel(int n, uint32_t seed, int* sel, int nsel, int nrounds) {
    __shared__ unsigned long long arr[4096];
    int tid = threadIdx.x, NT = blockDim.x;
    int vals[4];
    for (int t = 0; t < 4; t++) { int i = tid + t*NT; if (i < n) vals[t] = i; }
    uint32_t k0 = 0u, k1 = seed;
    for (int r = 0; r < nrounds; r++) {
        uint32_t nk0, nk1, sk0, sk1;
        tf2x32(k0, k1, 0u, 0u, nk0, nk1);   // new key = block(key,0,0)
        tf2x32(k0, k1, 0u, 1u, sk0, sk1);   // subkey  = block(key,0,1)
        k0 = nk0; k1 = nk1;
        for (int t = 0; t < 4; t++) {
            int i = tid + t*NT;
            if (i < n) {
                uint32_t o0, o1;
                tf2x32(sk0, sk1, 0u, (uint32_t)i, o0, o1);
                uint32_t bits = o0 ^ o1;  // partitionable 32-bit fold
                arr[i] = ((unsigned long long)bits << 24) |
                         ((unsigned long long)(unsigned)i << 12) |
                         (unsigned long long)(unsigned)vals[t];
            }
        }
        __syncthreads();
        for (int k = 2; k <= n; k <<= 1) {
            for (int j = k >> 1; j > 0; j >>= 1) {
                for (int t = 0; t < 4; t++) {
                    int i = tid + t*NT;
                    if (i < n) {
                        int ixj = i ^ j;
                        if (ixj > i && ixj < n) {
                            unsigned long long a = arr[i], c = arr[ixj];
                            bool up = ((i & k) == 0);
                            if ((a > c) == up) { arr[i] = c; arr[ixj] = a; }
                        }
                    }
                }
                __syncthreads();
            }
        }
        for (int t = 0; t < 4; t++) {
            int i = tid + t*NT;
            if (i < n) vals[t] = (int)(arr[i] & 0xFFFull);
        }
        __syncthreads();
    }
    for (int t = 0; t < 4; t++) { int i = tid + t*NT; if (i < nsel) sel[i] = vals[t]; }
}

// ---------------- fused column-normalize of all five (3,E) direction matrices ----------------
__global__ void normcols_all_kernel(const float* __restrict__ s0, float* __restrict__ d0,
                                    const float* __restrict__ s1, float* __restrict__ d1,
                                    const float* __restrict__ s2, float* __restrict__ d2,
                                    const float* __restrict__ s3, float* __restrict__ d3,
                                    const float* __restrict__ s4, float* __restrict__ d4) {
    int seg = blockIdx.y;
    const float* src; float* dst; int E;
    switch (seg) {
        case 0: src = s0; dst = d0; E = 128; break;
        case 1: src = s1; dst = d1; E = 256; break;
        case 2: src = s2; dst = d2; E = 512; break;
        case 3: src = s3; dst = d3; E = 1024; break;
        default: src = s4; dst = d4; E = 4096; break;
    }
    int e = blockIdx.x * blockDim.x + threadIdx.x;
    if (e >= E) return;
    float a = src[e], b = src[E + e], c = src[2*E + e];
    float nn = sqrtf(a*a + b*b + c*c);
    nn = fmaxf(nn, 1e-12f);
    dst[e] = a / nn; dst[E + e] = b / nn; dst[2*E + e] = c / nn;
}

// ---------------- incremental KNN + fused nd ----------------
// One block per (vertex, batch). Phase 1: 256 threads compute all VN distances into
// smem AND keep per-thread min as packed (ordered-dist | idx) 64-bit key.
// Rounds: warp 0 only, no block barriers: argmin over 256 keys, remove winner,
// rescan only the owner thread's VN/256 candidates.
__device__ __forceinline__ unsigned long long packkey(float d, int j) {
    uint32_t u = __float_as_uint(d);
    u = (u & 0x80000000u) ? ~u : (u | 0x80000000u);  // order-preserving for all floats
    return ((unsigned long long)u << 32) | (uint32_t)j;
}

__global__ void knn_nd_kernel(const float* __restrict__ verts, int* __restrict__ idx_out,
                              float* __restrict__ nd_out, int VN) {
    extern __shared__ float sdist[];                 // VN floats
    __shared__ unsigned long long s_tkey[256];
    __shared__ int s_win[NEI];
    int i = blockIdx.x, b = blockIdx.y;
    int tid = threadIdx.x;
    const float* vb = verts + (size_t)b * VN * 3;
    float vix = vb[i*3+0], viy = vb[i*3+1], viz = vb[i*3+2];
    float sqi = vix*vix + viy*viy + viz*viz;
    const float FINF = __int_as_float(0x7f800000);

    unsigned long long lkey = 0xFFFFFFFFFFFFFFFFull;
    for (int j = tid; j < VN; j += 256) {
        float x = vb[j*3+0], y = vb[j*3+1], z = vb[j*3+2];
        float d = sqi + (x*x + y*y + z*z) - 2.f*(vix*x + viy*y + viz*z);
        if (j == i) d = FINF;
        sdist[j] = d;
        unsigned long long k = packkey(d, j);
        if (k < lkey) lkey = k;
    }
    s_tkey[tid] = lkey;
    __syncthreads();

    if (tid < 32) {
        int nq = VN >> 8;   // candidates per slot (16 / 4 / 1)
        for (int r = 0; r < NEI; r++) {
            unsigned long long bk = 0xFFFFFFFFFFFFFFFFull;
            #pragma unroll
            for (int q = 0; q < 8; q++) {
                unsigned long long kk = s_tkey[tid + 32*q];
                if (kk < bk) bk = kk;
            }
            #pragma unroll
            for (int off = 16; off; off >>= 1) {
                unsigned long long o = __shfl_down_sync(0xffffffffu, bk, off);
                if (o < bk) bk = o;
            }
            bk = __shfl_sync(0xffffffffu, bk, 0);
            int j = (int)(bk & 0xFFFFFFFFull);
            if (tid == 0) { s_win[r] = j; sdist[j] = FINF; }
            __syncwarp();
            int slot = j & 255;
            unsigned long long nk = 0xFFFFFFFFFFFFFFFFull;
            if (tid < nq) {
                int jj = slot + (tid << 8);
                nk = packkey(sdist[jj], jj);
            }
            #pragma unroll
            for (int off = 16; off; off >>= 1) {
                unsigned long long o = __shfl_down_sync(0xffffffffu, nk, off);
                if (o < nk) nk = o;
            }
            if (tid == 0) s_tkey[slot] = nk;
            __syncwarp();
        }
    }
    __syncthreads();

    // epilogue: write idx + normalized neighbor directions
    if (tid < NEI) {
        int j = s_win[tid];
        size_t base = ((size_t)b * VN + i) * NEI + tid;
        idx_out[base] = j;
        float dx = vb[j*3+0] - vix;
        float dy = vb[j*3+1] - viy;
        float dz = vb[j*3+2] - viz;
        float nn = fmaxf(sqrtf(dx*dx + dy*dy + dz*dz), 1e-12f);
        nd_out[base*3+0] = dx / nn;
        nd_out[base*3+1] = dy / nn;
        nd_out[base*3+2] = dz / nn;
    }
}

// ---------------- conv_surface: 8 vertices per block, sd held in registers ----------------
#define CS_VPB 8
__global__ void conv_surface_kernel(const float* __restrict__ nd, const float* __restrict__ sd,
                                    float* __restrict__ fm0) {
    int v0 = blockIdx.x * CS_VPB, b = blockIdx.y;
    __shared__ float snd[CS_VPB][NEI*3];
    __shared__ float sm[CS_VPB][128];
    int tid = threadIdx.x;  // 128 threads, tid = e
    size_t base = ((size_t)b * V0 + v0) * NEI * 3;
    for (int i = tid; i < CS_VPB*NEI*3; i += 128)
        snd[i / (NEI*3)][i % (NEI*3)] = nd[base + i];
    __syncthreads();
    float s0 = sd[tid], s1 = sd[128 + tid], s2 = sd[256 + tid];
    const float NINF = -__int_as_float(0x7f800000);
    #pragma unroll
    for (int vv = 0; vv < CS_VPB; vv++) {
        float m = NINF;
        #pragma unroll
        for (int n = 0; n < NEI; n++) {
            float th = snd[vv][3*n]*s0 + snd[vv][3*n+1]*s1 + snd[vv][3*n+2]*s2;
            m = fmaxf(m, fmaxf(th, 0.f));
        }
        sm[vv][tid] = m;
    }
    __syncthreads();
    for (int i = tid; i < CS_VPB*32; i += 128) {
        int vv = i >> 5, c = i & 31;
        float r = sm[vv][c] + sm[vv][32 + c] + sm[vv][64 + c] + sm[vv][96 + c];
        fm0[((size_t)b * V0 + v0 + vv) * 32 + c] = fmaxf(r, 0.f);
    }
}

// ---------------- GEMM + bias, double-buffered ----------------
// 128x64 tile, 256 threads, 8x4 microtile, float4 loads, 1 barrier per k-tile.
// Requirements: M%128==0, N%64==0, K%16==0.
__global__ void gemm_bias_kernel(const float* __restrict__ A, const float* __restrict__ W,
                                 const float* __restrict__ bias, float* __restrict__ C,
                                 int M, int K, int N) {
    __shared__ float As[2][16][132];
    __shared__ float Bs[2][16][64];
    int bn = blockIdx.x * 64, bm = blockIdx.y * 128;
    int tid = threadIdx.x;
    int tx = tid & 15, ty = tid >> 4;
    float acc[8][4];
    #pragma unroll
    for (int j = 0; j < 4; j++) {
        float bv = bias[bn + tx*4 + j];
        #pragma unroll
        for (int i = 0; i < 8; i++) acc[i][j] = bv;
    }
    int mmA = tid >> 2;          // 0..63
    int kk4 = (tid & 3) * 4;     // 0,4,8,12
    int kkB = tid >> 4;          // 0..15
    int nn4 = (tid & 15) * 4;    // 0..60

    // prologue: load tile 0 into buffer 0
    {
        float4 a0 = *(const float4*)&A[(size_t)(bm + mmA) * K + kk4];
        float4 a1 = *(const float4*)&A[(size_t)(bm + mmA + 64) * K + kk4];
        float4 w0 = *(const float4*)&W[(size_t)kkB * N + bn + nn4];
        As[0][kk4+0][mmA] = a0.x; As[0][kk4+1][mmA] = a0.y;
        As[0][kk4+2][mmA] = a0.z; As[0][kk4+3][mmA] = a0.w;
        As[0][kk4+0][mmA+64] = a1.x; As[0][kk4+1][mmA+64] = a1.y;
        As[0][kk4+2][mmA+64] = a1.z; As[0][kk4+3][mmA+64] = a1.w;
        *(float4*)&Bs[0][kkB][nn4] = w0;
    }
    __syncthreads();
    int pb = 0;
    for (int k0 = 0; k0 < K; k0 += 16) {
        float4 pa0, pa1, pw;
        bool has = (k0 + 16) < K;
        if (has) {
            pa0 = *(const float4*)&A[(size_t)(bm + mmA) * K + k0 + 16 + kk4];
            pa1 = *(const float4*)&A[(size_t)(bm + mmA + 64) * K + k0 + 16 + kk4];
            pw  = *(const float4*)&W[(size_t)(k0 + 16 + kkB) * N + bn + nn4];
        }
        #pragma unroll
        for (int kk = 0; kk < 16; kk++) {
            float a[8], bv[4];
            *(float4*)&a[0] = *(const float4*)&As[pb][kk][ty*8];
            *(float4*)&a[4] = *(const float4*)&As[pb][kk][ty*8 + 4];
            *(float4*)&bv[0] = *(const float4*)&Bs[pb][kk][tx*4];
            #pragma unroll
            for (int i = 0; i < 8; i++)
                #pragma unroll
                for (int j = 0; j < 4; j++) acc[i][j] += a[i] * bv[j];
        }
        if (has) {
            int nb = pb ^ 1;
            As[nb][kk4+0][mmA] = pa0.x; As[nb][kk4+1][mmA] = pa0.y;
            As[nb][kk4+2][mmA] = pa0.z; As[nb][kk4+3][mmA] = pa0.w;
            As[nb][kk4+0][mmA+64] = pa1.x; As[nb][kk4+1][mmA+64] = pa1.y;
            As[nb][kk4+2][mmA+64] = pa1.z; As[nb][kk4+3][mmA+64] = pa1.w;
            *(float4*)&Bs[nb][kkB][nn4] = pw;
            __syncthreads();
            pb = nb;
        }
    }
    #pragma unroll
    for (int i = 0; i < 8; i++) {
        float4 o = make_float4(acc[i][0], acc[i][1], acc[i][2], acc[i][3]);
        *(float4*)&C[(size_t)(bm + ty*8 + i) * N + bn + tx*4] = o;
    }
}

// ---------------- conv_layer aggregation, float2 path ----------------
// out[b,v,c] = f[b,v,c] + sum_s max_n relu(nd . sd[:, s*C+c]) * f[b,idx[n], C + s*C + c]
__global__ void conv_layer_kernel(const float* __restrict__ f, const int* __restrict__ idx,
                                  const float* __restrict__ nd, const float* __restrict__ sd,
                                  float* __restrict__ out, int VN, int C, int do_relu,
                                  int VPB, int CT) {
    int b = blockIdx.y;
    int v0 = blockIdx.x * VPB;
    __shared__ float snd[8*NEI*3];
    __shared__ int   sidx[8*NEI];
    int tid = threadIdx.x;  // 256
    size_t ibase = ((size_t)b * VN + v0) * NEI;
    for (int i = tid; i < VPB*NEI; i += 256)   sidx[i] = idx[ibase + i];
    for (int i = tid; i < VPB*NEI*3; i += 256) snd[i]  = nd[ibase*3 + i];
    __syncthreads();
    int vloc = tid / CT, lc = tid % CT;
    int v = v0 + vloc;
    const float* fb = f + (size_t)b * VN * 5 * C;
    const float* myS = snd + vloc * NEI * 3;
    const int*   myI = sidx + vloc * NEI;
    int C2 = C >> 1, C4 = 4 * C;
    const float NINF = -__int_as_float(0x7f800000);
    for (int cp = lc; cp < C2; cp += CT) {
        float2 sx0 = ((const float2*)(sd + 0*C4 + 0*C))[cp];
        float2 sx1 = ((const float2*)(sd + 0*C4 + 1*C))[cp];
        float2 sx2 = ((const float2*)(sd + 0*C4 + 2*C))[cp];
        float2 sx3 = ((const float2*)(sd + 0*C4 + 3*C))[cp];
        float2 sy0 = ((const float2*)(sd + 1*C4 + 0*C))[cp];
        float2 sy1 = ((const float2*)(sd + 1*C4 + 1*C))[cp];
        float2 sy2 = ((const float2*)(sd + 1*C4 + 2*C))[cp];
        float2 sy3 = ((const float2*)(sd + 1*C4 + 3*C))[cp];
        float2 sz0 = ((const float2*)(sd + 2*C4 + 0*C))[cp];
        float2 sz1 = ((const float2*)(sd + 2*C4 + 1*C))[cp];
        float2 sz2 = ((const float2*)(sd + 2*C4 + 2*C))[cp];
        float2 sz3 = ((const float2*)(sd + 2*C4 + 3*C))[cp];
        float2 a0 = make_float2(NINF, NINF), a1 = a0, a2 = a0, a3 = a0;
        #pragma unroll 4
        for (int n = 0; n < NEI; n++) {
            float dx = myS[3*n], dy = myS[3*n+1], dz = myS[3*n+2];
            const float2* fj = (const float2*)(fb + (size_t)myI[n] * 5 * C + C);
            float2 f0 = fj[0*C2 + cp], f1 = fj[1*C2 + cp], f2 = fj[2*C2 + cp], f3 = fj[3*C2 + cp];
            float t0x = fmaxf(dx*sx0.x + dy*sy0.x + dz*sz0.x, 0.f);
            float t0y = fmaxf(dx*sx0.y + dy*sy0.y + dz*sz0.y, 0.f);
            float t1x = fmaxf(dx*sx1.x + dy*sy1.x + dz*sz1.x, 0.f);
            float t1y = fmaxf(dx*sx1.y + dy*sy1.y + dz*sz1.y, 0.f);
            float t2x = fmaxf(dx*sx2.x + dy*sy2.x + dz*sz2.x, 0.f);
            float t2y = fmaxf(dx*sx2.y + dy*sy2.y + dz*sz2.y, 0.f);
            float t3x = fmaxf(dx*sx3.x + dy*sy3.x + dz*sz3.x, 0.f);
            float t3y = fmaxf(dx*sx3.y + dy*sy3.y + dz*sz3.y, 0.f);
            a0.x = fmaxf(a0.x, t0x * f0.x); a0.y = fmaxf(a0.y, t0y * f0.y);
            a1.x = fmaxf(a1.x, t1x * f1.x); a1.y = fmaxf(a1.y, t1y * f1.y);
            a2.x = fmaxf(a2.x, t2x * f2.x); a2.y = fmaxf(a2.y, t2y * f2.y);
            a3.x = fmaxf(a3.x, t3x * f3.x); a3.y = fmaxf(a3.y, t3y * f3.y);
        }
        float2 ctr = ((const float2*)(fb + (size_t)v * 5 * C))[cp];
        float rx = ctr.x + ((a0.x + a1.x) + (a2.x + a3.x));
        float ry = ctr.y + ((a0.y + a1.y) + (a2.y + a3.y));
        if (do_relu) { rx = fmaxf(rx, 0.f); ry = fmaxf(ry, 0.f); }
        ((float2*)(out + ((size_t)b * VN + v) * C))[cp] = make_float2(rx, ry);
    }
}

// ---------------- pool: max over neighbors of selected rows, float2 path ----------------
__global__ void pool_kernel(const float* __restrict__ verts, const float* __restrict__ fm,
                            const int* __restrict__ idx, const int* __restrict__ sel,
                            float* __restrict__ vout, float* __restrict__ fout,
                            int VN, int C, int VOUT, int VPB, int CT) {
    int i0 = blockIdx.x * VPB, b = blockIdx.y;
    __shared__ int sidx[8][NEI];
    __shared__ int sr[8];
    int tid = threadIdx.x;  // 256
    int vloc = tid / CT, lc = tid % CT;
    if (lc == 0) sr[vloc] = sel[i0 + vloc];
    __syncthreads();
    int r = sr[vloc];
    if (lc < NEI) sidx[vloc][lc] = idx[((size_t)b * VN + r) * NEI + lc];
    if (lc < 3)
        vout[((size_t)b * VOUT + i0 + vloc) * 3 + lc] = verts[((size_t)b * VN + r) * 3 + lc];
    __syncthreads();
    const float NINF = -__int_as_float(0x7f800000);
    int C2 = C >> 1;
    for (int cp = lc; cp < C2; cp += CT) {
        float2 m = make_float2(NINF, NINF);
        #pragma unroll 4
        for (int n = 0; n < NEI; n++) {
            float2 x = ((const float2*)(fm + ((size_t)b * VN + sidx[vloc][n]) * C))[cp];
            m.x = fmaxf(m.x, x.x); m.y = fmaxf(m.y, x.y);
        }
        ((float2*)(fout + ((size_t)b * VOUT + i0 + vloc) * C))[cp] = m;
    }
}

// ---------------- final transpose: (b, v, c) -> (b, c, v) ----------------
__global__ void transpose_kernel(const float* __restrict__ fm4, float* __restrict__ out) {
    __shared__ float tile[32][33];
    int b = blockIdx.z;
    int v0 = blockIdx.x * 32, c0 = blockIdx.y * 32;
    int x = threadIdx.x, y = threadIdx.y;
    for (int yy = y; yy < 32; yy += 8)
        tile[yy][x] = fm4[((size_t)b * V2 + v0 + yy) * 1024 + c0 + x];
    __syncthreads();
    for (int yy = y; yy < 32; yy += 8)
        out[((size_t)b * 1024 + c0 + yy) * V2 + v0 + x] = tile[x][yy];
}

// ---------------- launch ----------------
extern "C" void kernel_launch(void* const* d_in, const int* in_sizes, int n_in,
                              void* d_out, int out_size) {
    const float* verts = (const float*)d_in[0];
    const float* dirs0 = (const float*)d_in[1];
    const float* W1 = (const float*)d_in[2];
    const float* b1 = (const float*)d_in[3];
    const float* D1 = (const float*)d_in[4];
    const float* W2 = (const float*)d_in[5];
    const float* b2 = (const float*)d_in[6];
    const float* D2 = (const float*)d_in[7];
    const float* W3 = (const float*)d_in[8];
    const float* b3 = (const float*)d_in[9];
    const float* D3 = (const float*)d_in[10];
    const float* W4 = (const float*)d_in[11];
    const float* b4 = (const float*)d_in[12];
    const float* D4 = (const float*)d_in[13];
    float* out = (float*)d_out;

    float *sd0, *sd1, *sd2, *sd3, *sd4;
    float *nd0, *nd1, *nd2;
    float *fm0, *f1, *fm1, *v1, *fm1p, *f2, *fm2, *f3, *fm3, *v2, *fm3p, *f4, *fm4;
    int *sel1, *sel2, *idx0, *idx1, *idx2;
    cudaGetSymbolAddress((void**)&sd0, g_sd0);
    cudaGetSymbolAddress((void**)&sd1, g_sd1);
    cudaGetSymbolAddress((void**)&sd2, g_sd2);
    cudaGetSymbolAddress((void**)&sd3, g_sd3);
    cudaGetSymbolAddress((void**)&sd4, g_sd4);
    cudaGetSymbolAddress((void**)&sel1, g_sel1);
    cudaGetSymbolAddress((void**)&sel2, g_sel2);
    cudaGetSymbolAddress((void**)&idx0, g_idx0);
    cudaGetSymbolAddress((void**)&idx1, g_idx1);
    cudaGetSymbolAddress((void**)&idx2, g_idx2);
    cudaGetSymbolAddress((void**)&nd0, g_nd0);
    cudaGetSymbolAddress((void**)&nd1, g_nd1);
    cudaGetSymbolAddress((void**)&nd2, g_nd2);
    cudaGetSymbolAddress((void**)&fm0, g_fm0);
    cudaGetSymbolAddress((void**)&f1, g_f1);
    cudaGetSymbolAddress((void**)&fm1, g_fm1);
    cudaGetSymbolAddress((void**)&v1, g_v1);
    cudaGetSymbolAddress((void**)&fm1p, g_fm1p);
    cudaGetSymbolAddress((void**)&f2, g_f2);
    cudaGetSymbolAddress((void**)&fm2, g_fm2);
    cudaGetSymbolAddress((void**)&f3, g_f3);
    cudaGetSymbolAddress((void**)&fm3, g_fm3);
    cudaGetSymbolAddress((void**)&v2, g_v2);
    cudaGetSymbolAddress((void**)&fm3p, g_fm3p);
    cudaGetSymbolAddress((void**)&f4, g_f4);
    cudaGetSymbolAddress((void**)&fm4, g_fm4);

    // [0] direction bases, [1][2] permutations (independent prologue)
    normcols_all_kernel<<<dim3(32, 5), 128>>>(dirs0, sd0, D1, sd1, D2, sd2, D3, sd3, D4, sd4);
    perm_kernel<<<1, 1024>>>(4096, 42u, sel1, V1, 2);
    perm_kernel<<<1, 1024>>>(1024, 43u, sel2, V2, 1);

    // stage A (4096 verts) — [3] knn0 is the profiled launch next round
    knn_nd_kernel<<<dim3(V0, BB), 256, V0 * sizeof(float)>>>(verts, idx0, nd0, V0);
    conv_surface_kernel<<<dim3(V0 / CS_VPB, BB), 128>>>(nd0, sd0, fm0);
    gemm_bias_kernel<<<dim3(320/64, BB*V0/128), 256>>>(fm0, W1, b1, f1, BB*V0, 32, 320);
    conv_layer_kernel<<<dim3(V0/8, BB), 256>>>(f1, idx0, nd0, sd1, fm1, V0, 64, 1, 8, 32);
    pool_kernel<<<dim3(V1/8, BB), 256>>>(verts, fm1, idx0, sel1, v1, fm1p, V0, 64, V1, 8, 32);

    // stage B (1024 verts)
    knn_nd_kernel<<<dim3(V1, BB), 256, V1 * sizeof(float)>>>(v1, idx1, nd1, V1);
    gemm_bias_kernel<<<dim3(640/64, BB*V1/128), 256>>>(fm1p, W2, b2, f2, BB*V1, 64, 640);
    conv_layer_kernel<<<dim3(V1/4, BB), 256>>>(f2, idx1, nd1, sd2, fm2, V1, 128, 1, 4, 64);
    gemm_bias_kernel<<<dim3(1280/64, BB*V1/128), 256>>>(fm2, W3, b3, f3, BB*V1, 128, 1280);
    conv_layer_kernel<<<dim3(V1/2, BB), 256>>>(f3, idx1, nd1, sd3, fm3, V1, 256, 1, 2, 128);
    pool_kernel<<<dim3(V2/2, BB), 256>>>(v1, fm3, idx1, sel2, v2, fm3p, V1, 256, V2, 2, 128);

    // stage C (256 verts)
    knn_nd_kernel<<<dim3(V2, BB), 256, V2 * sizeof(float)>>>(v2, idx2, nd2, V2);
    gemm_bias_kernel<<<dim3(5120/64, BB*V2/128), 256>>>(fm3p, W4, b4, f4, BB*V2, 256, 5120);
    conv_layer_kernel<<<dim3(V2, BB), 256>>>(f4, idx2, nd2, sd4, fm4, V2, 1024, 0, 1, 256);

    // output transpose (b, v, c) -> (b, c, v, 1)
    transpose_kernel<<<dim3(V2 / 32, 1024 / 32, BB), dim3(32, 8)>>>(fm4, out);
}